// round 8
// baseline (speedup 1.0000x reference)
#include <cuda_runtime.h>
#include <cuda_bf16.h>
#include <cstdint>

#define NS    4096
#define ND    64
#define NF    9
#define NDIM  128
#define NBH   64
#define SCHUNKS 8
#define SCHUNK  512

__device__ float g_KVpart[SCHUNKS * NBH * ND * ND];  // 8.4 MB
__device__ float g_KV[NBH * ND * ND];                // 1 MB

typedef unsigned int u32;
typedef unsigned long long u64;

// ---------------- helpers ----------------
__device__ __forceinline__ u32 smem_u32(const void* p) {
    u32 a;
    asm("{ .reg .u64 t; cvta.to.shared.u64 t, %1; cvt.u32.u64 %0, t; }" : "=r"(a) : "l"(p));
    return a;
}

// Swizzled byte offset inside a [rows][64 bf16] tile (128B rows, 8 chunks of
// 16B, chunk ^= row&7). Conflict-free for u64 row-major stores AND ldmatrix.
__device__ __forceinline__ u32 swoff(int row, int col) {
    return (u32)((row << 7) + ((((col >> 3) ^ row) & 7) << 4) + ((col & 7) << 1));
}

// two floats -> packed bf16 hi pair + bf16 residual lo pair (x in low half)
__device__ __forceinline__ void split2(float x, float y, u32& hi, u32& lo) {
    __nv_bfloat16 hx = __float2bfloat16_rn(x);
    __nv_bfloat16 hy = __float2bfloat16_rn(y);
    __nv_bfloat16 lx = __float2bfloat16_rn(x - __bfloat162float(hx));
    __nv_bfloat16 ly = __float2bfloat16_rn(y - __bfloat162float(hy));
    hi = (u32)__bfloat16_as_ushort(hx) | ((u32)__bfloat16_as_ushort(hy) << 16);
    lo = (u32)__bfloat16_as_ushort(lx) | ((u32)__bfloat16_as_ushort(ly) << 16);
}
// float4 -> two u64 (hi-words, lo-words) for row-major bf16 store
__device__ __forceinline__ void split4_u64(float4 v, u64& hi, u64& lo) {
    u32 h0, l0, h1, l1;
    split2(v.x, v.y, h0, l0);
    split2(v.z, v.w, h1, l1);
    hi = (u64)h0 | ((u64)h1 << 32);
    lo = (u64)l0 | ((u64)l1 << 32);
}

__device__ __forceinline__ void ldsm_x4(u32 r[4], u32 addr) {
    asm volatile("ldmatrix.sync.aligned.m8n8.x4.shared.b16 {%0,%1,%2,%3}, [%4];"
                 : "=r"(r[0]), "=r"(r[1]), "=r"(r[2]), "=r"(r[3]) : "r"(addr));
}
__device__ __forceinline__ void ldsm_x4_t(u32 r[4], u32 addr) {
    asm volatile("ldmatrix.sync.aligned.m8n8.x4.trans.shared.b16 {%0,%1,%2,%3}, [%4];"
                 : "=r"(r[0]), "=r"(r[1]), "=r"(r[2]), "=r"(r[3]) : "r"(addr));
}
__device__ __forceinline__ void ldsm_x2_t(u32& r0, u32& r1, u32 addr) {
    asm volatile("ldmatrix.sync.aligned.m8n8.x2.trans.shared.b16 {%0,%1}, [%2];"
                 : "=r"(r0), "=r"(r1) : "r"(addr));
}
__device__ __forceinline__ void mma16816(float* c, const u32* a, u32 b0, u32 b1) {
    asm volatile("mma.sync.aligned.m16n8k16.row.col.f32.bf16.bf16.f32 "
                 "{%0,%1,%2,%3}, {%4,%5,%6,%7}, {%8,%9}, {%0,%1,%2,%3};"
                 : "+f"(c[0]), "+f"(c[1]), "+f"(c[2]), "+f"(c[3])
                 : "r"(a[0]), "r"(a[1]), "r"(a[2]), "r"(a[3]), "r"(b0), "r"(b1));
}

// -------- routing (general path), NTHR threads --------
template <int NTHR>
__device__ __forceinline__ void route_rows(
    const float* __restrict__ Xt, const float* __restrict__ Xp, long tb,
    const float* sW, const float* sLam, float* sLamRow, int rows, int tid)
{
    const int RP = NTHR / 4;
    for (int r0 = 0; r0 < rows; r0 += RP) {
        const int g = r0 + (tid >> 2), q = tid & 3;
        const float* xptr = (q < 2) ? (Xt + tb + (long)g * ND + 32 * q)
                                    : (Xp + tb + (long)g * ND + 32 * (q - 2));
        float sc[NF];
        #pragma unroll
        for (int n = 0; n < NF; n++) sc[n] = 0.f;
        #pragma unroll
        for (int e4 = 0; e4 < 8; e4++) {
            float4 xv = *(const float4*)(xptr + 4 * e4);
            #pragma unroll
            for (int n = 0; n < NF; n++) {
                float4 wv = *(const float4*)(sW + n * NDIM + 32 * q + 4 * e4);
                sc[n] += xv.x * wv.x + xv.y * wv.y + xv.z * wv.z + xv.w * wv.w;
            }
        }
        #pragma unroll
        for (int n = 0; n < NF; n++) {
            sc[n] += __shfl_xor_sync(0xffffffffu, sc[n], 1);
            sc[n] += __shfl_xor_sync(0xffffffffu, sc[n], 2);
        }
        int best = 0;
        #pragma unroll
        for (int n = 1; n < NF; n++) if (sc[n] > sc[best]) best = n;
        best = __shfl_sync(0xffffffffu, best, (tid & 31) & ~3);
        if (q == 0) sLamRow[g] = sLam[best];
    }
}

// ==================== Phase A: KV partials via mma.sync ====================
// 256 thr, 8 warps. Out 64x64 (d x e). K = 512 s in 8 tiles of 64.
// smem tiles are row-major [s][64] bf16 hi/lo; transposition via ldsm.trans.
__global__ void __launch_bounds__(256) kv_tc(
    const float* __restrict__ Kt, const float* __restrict__ Kp,
    const float* __restrict__ Vg, const float* __restrict__ lambdas,
    const float* __restrict__ Wk)
{
    __shared__ char sKH[8192], sKL[8192], sVH[8192], sVL[8192];
    __shared__ float sW[NF * NDIM];
    __shared__ float sLam[NF];
    __shared__ float sLamRow[64];
    __shared__ int   sUni;

    const int tid = threadIdx.x;
    const int chunk = blockIdx.x, bh = blockIdx.y;

    if (tid == 0) {
        float l0 = lambdas[0]; int u = 1;
        sLam[0] = l0;
        #pragma unroll
        for (int n = 1; n < NF; n++) { float v = lambdas[n]; sLam[n] = v; u &= (v == l0); }
        sUni = u;
    }
    __syncthreads();
    const bool uniform = (sUni != 0);
    const float lam0 = sLam[0];
    if (!uniform) {
        for (int idx = tid; idx < NF * NDIM; idx += 256) sW[idx] = Wk[idx];
        __syncthreads();
    }

    const int w = tid >> 5, lane = tid & 31;
    const int wd = w & 3, we = w >> 2;
    const int g = lane >> 2, t4 = lane & 3;
    const u32 kh = smem_u32(sKH), kl = smem_u32(sKL);
    const u32 vh = smem_u32(sVH), vl = smem_u32(sVL);

    float acc[4][4];
    #pragma unroll
    for (int j = 0; j < 4; j++)
        #pragma unroll
        for (int c = 0; c < 4; c++) acc[j][c] = 0.f;

    const long base = ((long)bh * NS + (long)chunk * SCHUNK) * ND;
    const int sst = (tid >> 4);        // staging s row base (0..15)
    const int sc4 = (tid & 15);        // staging col quad

    float4 pf[8];   // prefetch: 4 x (Kdiff float4, V float4)
    if (uniform) {
        #pragma unroll
        for (int r = 0; r < 4; r++) {
            const int s = sst + 16 * r;
            const long off = base + (long)s * ND + 4 * sc4;
            float4 a = *(const float4*)(Kt + off);
            float4 b = *(const float4*)(Kp + off);
            float4 d;
            d.x = a.x - lam0 * b.x;  d.y = a.y - lam0 * b.y;
            d.z = a.z - lam0 * b.z;  d.w = a.w - lam0 * b.w;
            pf[2 * r] = d;
            pf[2 * r + 1] = *(const float4*)(Vg + off);
        }
    }

    for (int t = 0; t < SCHUNK / 64; t++) {
        const long tb = base + (long)t * 64 * ND;
        if (uniform) {
            #pragma unroll
            for (int r = 0; r < 4; r++) {
                const int s = sst + 16 * r;
                const u32 off = swoff(s, 4 * sc4);
                u64 hi, lo;
                split4_u64(pf[2 * r], hi, lo);
                *(u64*)(sKH + off) = hi;  *(u64*)(sKL + off) = lo;
                split4_u64(pf[2 * r + 1], hi, lo);
                *(u64*)(sVH + off) = hi;  *(u64*)(sVL + off) = lo;
            }
            __syncthreads();
            if (t < SCHUNK / 64 - 1) {
                const long nb = tb + (long)64 * ND;
                #pragma unroll
                for (int r = 0; r < 4; r++) {
                    const int s = sst + 16 * r;
                    const long off = nb + (long)s * ND + 4 * sc4;
                    float4 a = *(const float4*)(Kt + off);
                    float4 b = *(const float4*)(Kp + off);
                    float4 d;
                    d.x = a.x - lam0 * b.x;  d.y = a.y - lam0 * b.y;
                    d.z = a.z - lam0 * b.z;  d.w = a.w - lam0 * b.w;
                    pf[2 * r] = d;
                    pf[2 * r + 1] = *(const float4*)(Vg + off);
                }
            }
        } else {
            route_rows<256>(Kt, Kp, tb, sW, sLam, sLamRow, 64, tid);
            __syncthreads();
            #pragma unroll
            for (int r = 0; r < 4; r++) {
                const int s = sst + 16 * r;
                const float l = sLamRow[s];
                const long off = tb + (long)s * ND + 4 * sc4;
                float4 a = *(const float4*)(Kt + off);
                float4 b = *(const float4*)(Kp + off);
                float4 d;
                d.x = a.x - l * b.x;  d.y = a.y - l * b.y;
                d.z = a.z - l * b.z;  d.w = a.w - l * b.w;
                const u32 so = swoff(s, 4 * sc4);
                u64 hi, lo;
                split4_u64(d, hi, lo);
                *(u64*)(sKH + so) = hi;  *(u64*)(sKL + so) = lo;
                split4_u64(*(const float4*)(Vg + off), hi, lo);
                *(u64*)(sVH + so) = hi;  *(u64*)(sVL + so) = lo;
            }
            __syncthreads();
        }

        // MMA: A = Kd^T (m=d rows 16wd..), B = V^T (n=e cols 32we..)
        #pragma unroll
        for (int kk = 0; kk < 4; kk++) {
            const int k0 = 16 * kk;
            u32 aH[4], aL[4];
            const u32 aoff = swoff(k0 + (lane & 7) + 8 * (lane >> 4),
                                   16 * wd + 8 * ((lane >> 3) & 1));
            ldsm_x4_t(aH, kh + aoff);
            ldsm_x4_t(aL, kl + aoff);
            const int brow = k0 + (lane & 7) + 8 * ((lane >> 3) & 1);
            #pragma unroll
            for (int j = 0; j < 4; j++) {
                const u32 boff = swoff(brow, 32 * we + 8 * j);
                u32 bH0, bH1, bL0, bL1;
                ldsm_x2_t(bH0, bH1, vh + boff);
                ldsm_x2_t(bL0, bL1, vl + boff);
                mma16816(acc[j], aH, bH0, bH1);
                mma16816(acc[j], aH, bL0, bL1);
                mma16816(acc[j], aL, bH0, bH1);
            }
        }
        __syncthreads();
    }

    float* out = g_KVpart + ((long)chunk * NBH + bh) * (ND * ND);
    #pragma unroll
    for (int j = 0; j < 4; j++) {
        const int r0 = 16 * wd + g, e0 = 32 * we + 8 * j + 2 * t4;
        *(float2*)(out + r0 * ND + e0) = make_float2(acc[j][0], acc[j][1]);
        *(float2*)(out + (r0 + 8) * ND + e0) = make_float2(acc[j][2], acc[j][3]);
    }
}

// ==================== Reduce partials -> g_KV ====================
__global__ void __launch_bounds__(256) reduce_kernel()
{
    const int idx = blockIdx.x * 256 + threadIdx.x;   // over 65536 float4
    const float4* p = (const float4*)g_KVpart;
    float4 s = p[idx];
    #pragma unroll
    for (int c = 1; c < SCHUNKS; c++) {
        float4 v = p[(long)c * (NBH * ND * ND / 4) + idx];
        s.x += v.x; s.y += v.y; s.z += v.z; s.w += v.w;
    }
    ((float4*)g_KV)[idx] = s;
}

// ==================== Phase B: O = Qd @ KV via mma.sync ====================
// 256 thr, 8 warps; 2 tiles of 128 s-rows per block with prefetch.
#define PB_QH 0
#define PB_QL 16384
#define PB_BH 32768
#define PB_BL 40960
#define PB_W  49152
#define PB_LR 53760
#define PB_LM 54272
#define PB_UN 54336
#define PB_TOTAL 54400

__global__ void __launch_bounds__(256) out_tc(
    const float* __restrict__ Qt, const float* __restrict__ Qp,
    const float* __restrict__ lambdas, const float* __restrict__ Wq,
    float* __restrict__ O)
{
    extern __shared__ char smem[];
    char* sQH = smem + PB_QH;
    char* sQL = smem + PB_QL;
    char* sBH = smem + PB_BH;
    char* sBL = smem + PB_BL;
    float* sW = (float*)(smem + PB_W);
    float* sLamRow = (float*)(smem + PB_LR);
    float* sLam = (float*)(smem + PB_LM);
    int* sUni = (int*)(smem + PB_UN);

    const int tid = threadIdx.x;
    const int st = blockIdx.x, bh = blockIdx.y;

    if (tid == 0) {
        float l0 = lambdas[0]; int u = 1;
        sLam[0] = l0;
        #pragma unroll
        for (int n = 1; n < NF; n++) { float v = lambdas[n]; sLam[n] = v; u &= (v == l0); }
        *sUni = u;
    }
    __syncthreads();
    const bool uniform = (*sUni != 0);
    const float lam0 = sLam[0];

    // stage KV row-major [d][e] bf16 hi/lo (contiguous g_KV reads)
    {
        const float* kv = g_KV + (long)bh * ND * ND;
        #pragma unroll
        for (int r = 0; r < 4; r++) {
            const int idx = tid + 256 * r;
            const int d = idx >> 4, c4 = idx & 15;
            float4 v = *(const float4*)(kv + d * ND + 4 * c4);
            u64 hi, lo; split4_u64(v, hi, lo);
            const u32 off = swoff(d, 4 * c4);
            *(u64*)(sBH + off) = hi;
            *(u64*)(sBL + off) = lo;
        }
    }
    if (!uniform) {
        for (int idx = tid; idx < NF * NDIM; idx += 256) sW[idx] = Wq[idx];
    }

    const int w = tid >> 5, lane = tid & 31;
    const int g = lane >> 2, t4 = lane & 3;
    const u32 qh = smem_u32(sQH), ql = smem_u32(sQL);
    const u32 bhp = smem_u32(sBH), blp = smem_u32(sBL);
    const int sst = tid >> 1;          // staging: s rows (tid>>1) + 128r? no:
    // staging mapping: idx = tid + 256*r, r 0..7; s = idx>>4 (0..127), c4 = idx&15

    const long base = ((long)bh * NS + (long)st * 256) * ND;

    float4 pf[8];
    if (uniform) {
        #pragma unroll
        for (int r = 0; r < 8; r++) {
            const int idx = tid + 256 * r;
            const int s = idx >> 4, c4 = idx & 15;
            const long off = base + (long)s * ND + 4 * c4;
            float4 a = *(const float4*)(Qt + off);
            float4 b = *(const float4*)(Qp + off);
            float4 d;
            d.x = a.x - lam0 * b.x;  d.y = a.y - lam0 * b.y;
            d.z = a.z - lam0 * b.z;  d.w = a.w - lam0 * b.w;
            pf[r] = d;
        }
    }

    for (int t = 0; t < 2; t++) {
        const long tb = base + (long)t * 128 * ND;
        if (uniform) {
            #pragma unroll
            for (int r = 0; r < 8; r++) {
                const int idx = tid + 256 * r;
                const int s = idx >> 4, c4 = idx & 15;
                u64 hi, lo; split4_u64(pf[r], hi, lo);
                const u32 off = swoff(s, 4 * c4);
                *(u64*)(sQH + off) = hi;
                *(u64*)(sQL + off) = lo;
            }
            __syncthreads();
            if (t == 0) {
                const long nb = tb + (long)128 * ND;
                #pragma unroll
                for (int r = 0; r < 8; r++) {
                    const int idx = tid + 256 * r;
                    const int s = idx >> 4, c4 = idx & 15;
                    const long off = nb + (long)s * ND + 4 * c4;
                    float4 a = *(const float4*)(Qt + off);
                    float4 b = *(const float4*)(Qp + off);
                    float4 d;
                    d.x = a.x - lam0 * b.x;  d.y = a.y - lam0 * b.y;
                    d.z = a.z - lam0 * b.z;  d.w = a.w - lam0 * b.w;
                    pf[r] = d;
                }
            }
        } else {
            route_rows<256>(Qt, Qp, tb, sW, sLam, sLamRow, 128, tid);
            __syncthreads();
            #pragma unroll
            for (int r = 0; r < 8; r++) {
                const int idx = tid + 256 * r;
                const int s = idx >> 4, c4 = idx & 15;
                const float l = sLamRow[s];
                const long off = tb + (long)s * ND + 4 * c4;
                float4 a = *(const float4*)(Qt + off);
                float4 b = *(const float4*)(Qp + off);
                float4 d;
                d.x = a.x - l * b.x;  d.y = a.y - l * b.y;
                d.z = a.z - l * b.z;  d.w = a.w - l * b.w;
                u64 hi, lo; split4_u64(d, hi, lo);
                const u32 off2 = swoff(s, 4 * c4);
                *(u64*)(sQH + off2) = hi;
                *(u64*)(sQL + off2) = lo;
            }
            __syncthreads();
        }

        float acc[8][4];
        #pragma unroll
        for (int j = 0; j < 8; j++)
            #pragma unroll
            for (int c = 0; c < 4; c++) acc[j][c] = 0.f;

        // A = Qd row-major (non-trans), B = KV stored [d][e] -> trans
        #pragma unroll
        for (int kk = 0; kk < 4; kk++) {
            const int k0 = 16 * kk;
            u32 aH[4], aL[4];
            const u32 aoff = swoff(16 * w + (lane & 15), k0 + 8 * (lane >> 4));
            ldsm_x4(aH, qh + aoff);
            ldsm_x4(aL, ql + aoff);
            const int brow = k0 + (lane & 7) + 8 * ((lane >> 3) & 1);
            #pragma unroll
            for (int j = 0; j < 8; j++) {
                const u32 boff = swoff(brow, 8 * j);
                u32 bH0, bH1, bL0, bL1;
                ldsm_x2_t(bH0, bH1, bhp + boff);
                ldsm_x2_t(bL0, bL1, blp + boff);
                mma16816(acc[j], aH, bH0, bH1);
                mma16816(acc[j], aH, bL0, bL1);
                mma16816(acc[j], aL, bH0, bH1);
            }
        }

        float* out = O + tb;
        #pragma unroll
        for (int j = 0; j < 8; j++) {
            const int r0 = 16 * w + g, e0 = 8 * j + 2 * t4;
            *(float2*)(out + (long)r0 * ND + e0) = make_float2(acc[j][0], acc[j][1]);
            *(float2*)(out + (long)(r0 + 8) * ND + e0) = make_float2(acc[j][2], acc[j][3]);
        }
        __syncthreads();
    }
}

extern "C" void kernel_launch(void* const* d_in, const int* in_sizes, int n_in,
                              void* d_out, int out_size)
{
    const float* Qt  = (const float*)d_in[0];
    const float* Qp  = (const float*)d_in[1];
    const float* Kt  = (const float*)d_in[2];
    const float* Kp  = (const float*)d_in[3];
    const float* Vg  = (const float*)d_in[4];
    const float* lam = (const float*)d_in[5];
    const float* Wq  = (const float*)d_in[6];
    const float* Wk  = (const float*)d_in[7];
    float* O = (float*)d_out;

    static bool attr_set = false;
    if (!attr_set) {
        cudaFuncSetAttribute(out_tc, cudaFuncAttributeMaxDynamicSharedMemorySize, PB_TOTAL);
        attr_set = true;
    }

    kv_tc<<<dim3(SCHUNKS, NBH), 256>>>(Kt, Kp, Vg, lam, Wk);
    reduce_kernel<<<(NBH * ND * ND / 4) / 256, 256>>>();
    out_tc<<<dim3(NS / 256, NBH), 256, PB_TOTAL>>>(Qt, Qp, lam, Wq, O);
}

// round 10
// speedup vs baseline: 1.0966x; 1.0966x over previous
#include <cuda_runtime.h>
#include <cuda_bf16.h>
#include <cstdint>

#define NS    4096
#define ND    64
#define NF    9
#define NDIM  128
#define NBH   64
#define SCHUNKS 8
#define SCHUNK  512

__device__ float g_KVpart[SCHUNKS * NBH * ND * ND];  // 8.4 MB
__device__ float g_KV[NBH * ND * ND];                // 1 MB

typedef unsigned int u32;
typedef unsigned long long u64;

// ---------------- helpers ----------------
__device__ __forceinline__ u32 smem_u32(const void* p) {
    u32 a;
    asm("{ .reg .u64 t; cvta.to.shared.u64 t, %1; cvt.u32.u64 %0, t; }" : "=r"(a) : "l"(p));
    return a;
}

#define CP16(dst, src) \
    asm volatile("cp.async.cg.shared.global [%0], [%1], 16;" :: "r"(dst), "l"(src))
#define CP_COMMIT() asm volatile("cp.async.commit_group;" ::: "memory")
#define CP_WAIT(n)  asm volatile("cp.async.wait_group %0;" :: "n"(n) : "memory")

// Swizzled byte offset inside a [rows][64 bf16] tile (128B rows, 8 chunks of
// 16B, chunk ^= row&7). Conflict-free for u64 row-major stores AND ldmatrix.
__device__ __forceinline__ u32 swoff(int row, int col) {
    return (u32)((row << 7) + ((((col >> 3) ^ row) & 7) << 4) + ((col & 7) << 1));
}

__device__ __forceinline__ void split2(float x, float y, u32& hi, u32& lo) {
    __nv_bfloat16 hx = __float2bfloat16_rn(x);
    __nv_bfloat16 hy = __float2bfloat16_rn(y);
    __nv_bfloat16 lx = __float2bfloat16_rn(x - __bfloat162float(hx));
    __nv_bfloat16 ly = __float2bfloat16_rn(y - __bfloat162float(hy));
    hi = (u32)__bfloat16_as_ushort(hx) | ((u32)__bfloat16_as_ushort(hy) << 16);
    lo = (u32)__bfloat16_as_ushort(lx) | ((u32)__bfloat16_as_ushort(ly) << 16);
}
__device__ __forceinline__ void split4_u64(float4 v, u64& hi, u64& lo) {
    u32 h0, l0, h1, l1;
    split2(v.x, v.y, h0, l0);
    split2(v.z, v.w, h1, l1);
    hi = (u64)h0 | ((u64)h1 << 32);
    lo = (u64)l0 | ((u64)l1 << 32);
}

__device__ __forceinline__ void ldsm_x4(u32 r[4], u32 addr) {
    asm volatile("ldmatrix.sync.aligned.m8n8.x4.shared.b16 {%0,%1,%2,%3}, [%4];"
                 : "=r"(r[0]), "=r"(r[1]), "=r"(r[2]), "=r"(r[3]) : "r"(addr));
}
__device__ __forceinline__ void ldsm_x4_t(u32 r[4], u32 addr) {
    asm volatile("ldmatrix.sync.aligned.m8n8.x4.trans.shared.b16 {%0,%1,%2,%3}, [%4];"
                 : "=r"(r[0]), "=r"(r[1]), "=r"(r[2]), "=r"(r[3]) : "r"(addr));
}
__device__ __forceinline__ void ldsm_x2_t(u32& r0, u32& r1, u32 addr) {
    asm volatile("ldmatrix.sync.aligned.m8n8.x2.trans.shared.b16 {%0,%1}, [%2];"
                 : "=r"(r0), "=r"(r1) : "r"(addr));
}
__device__ __forceinline__ void mma16816(float* c, const u32* a, u32 b0, u32 b1) {
    asm volatile("mma.sync.aligned.m16n8k16.row.col.f32.bf16.bf16.f32 "
                 "{%0,%1,%2,%3}, {%4,%5,%6,%7}, {%8,%9}, {%0,%1,%2,%3};"
                 : "+f"(c[0]), "+f"(c[1]), "+f"(c[2]), "+f"(c[3])
                 : "r"(a[0]), "r"(a[1]), "r"(a[2]), "r"(a[3]), "r"(b0), "r"(b1));
}

// -------- routing from raw smem tiles (64 rows, 256 threads, one pass) --------
__device__ __forceinline__ void route_smem(
    const float* __restrict__ rX, const float* __restrict__ rP,
    const float* sW, const float* sLam, float* sLamRow, int tid)
{
    const int g = tid >> 2, q = tid & 3;
    const float* xptr = (q < 2) ? (rX + g * ND + 32 * q)
                                : (rP + g * ND + 32 * (q - 2));
    float sc[NF];
    #pragma unroll
    for (int n = 0; n < NF; n++) sc[n] = 0.f;
    #pragma unroll
    for (int e4 = 0; e4 < 8; e4++) {
        float4 xv = *(const float4*)(xptr + 4 * e4);
        #pragma unroll
        for (int n = 0; n < NF; n++) {
            float4 wv = *(const float4*)(sW + n * NDIM + 32 * q + 4 * e4);
            sc[n] += xv.x * wv.x + xv.y * wv.y + xv.z * wv.z + xv.w * wv.w;
        }
    }
    #pragma unroll
    for (int n = 0; n < NF; n++) {
        sc[n] += __shfl_xor_sync(0xffffffffu, sc[n], 1);
        sc[n] += __shfl_xor_sync(0xffffffffu, sc[n], 2);
    }
    int best = 0;
    #pragma unroll
    for (int n = 1; n < NF; n++) if (sc[n] > sc[best]) best = n;
    best = __shfl_sync(0xffffffffu, best, (tid & 31) & ~3);
    if (q == 0) sLamRow[g] = sLam[best];
}

// ==================== Phase A: KV partials, cp.async depth-3 pipeline ====================
// dyn smem offsets (bytes)
#define KA_RAW(st, arr) (((st) * 3 + (arr)) * 16384)   // st 0..2; arr 0:K 1:K' 2:V
#define KA_KH 147456
#define KA_KL 155648
#define KA_VH 163840
#define KA_VL 172032
#define KA_W  180224
#define KA_LR 184832
#define KA_LM 185088
#define KA_UN 185152
#define KA_TOTAL 185216

__device__ __forceinline__ void kv_issue(
    u32 sb, int stage,
    const float* __restrict__ gK, const float* __restrict__ gP,
    const float* __restrict__ gV, long tb, int tid)
{
    const u32 dK = sb + KA_RAW(stage, 0);
    const u32 dP = sb + KA_RAW(stage, 1);
    const u32 dV = sb + KA_RAW(stage, 2);
    #pragma unroll
    for (int r = 0; r < 4; r++) {
        const int idx = tid + 256 * r;        // 16B chunk id, 1024 per array
        const u32 o = (u32)idx * 16;
        CP16(dK + o, gK + tb + (long)idx * 4);
        CP16(dP + o, gP + tb + (long)idx * 4);
        CP16(dV + o, gV + tb + (long)idx * 4);
    }
}

__global__ void __launch_bounds__(256) kv_tc(
    const float* __restrict__ Kt, const float* __restrict__ Kp,
    const float* __restrict__ Vg, const float* __restrict__ lambdas,
    const float* __restrict__ Wk)
{
    extern __shared__ char smem[];
    const u32 sb = smem_u32(smem);
    float* sW = (float*)(smem + KA_W);
    float* sLamRow = (float*)(smem + KA_LR);
    float* sLam = (float*)(smem + KA_LM);
    int* sUni = (int*)(smem + KA_UN);

    const int tid = threadIdx.x;
    const int chunk = blockIdx.x, bh = blockIdx.y;

    if (tid == 0) {
        float l0 = lambdas[0]; int u = 1;
        sLam[0] = l0;
        #pragma unroll
        for (int n = 1; n < NF; n++) { float v = lambdas[n]; sLam[n] = v; u &= (v == l0); }
        *sUni = u;
    }
    const long base = ((long)bh * NS + (long)chunk * SCHUNK) * ND;

    // prologue: issue tiles 0,1,2
    #pragma unroll
    for (int p = 0; p < 3; p++) {
        kv_issue(sb, p, Kt, Kp, Vg, base + (long)p * 64 * ND, tid);
        CP_COMMIT();
    }
    __syncthreads();
    const bool uniform = (*sUni != 0);
    const float lam0 = sLam[0];
    if (!uniform) {
        for (int idx = tid; idx < NF * NDIM; idx += 256) sW[idx] = Wk[idx];
    }

    const int w = tid >> 5, lane = tid & 31;
    const int wd = w & 3, we = w >> 2;
    const int g = lane >> 2, t4 = lane & 3;
    const u32 kh = sb + KA_KH, kl = sb + KA_KL;
    const u32 vh = sb + KA_VH, vl = sb + KA_VL;

    float acc[4][4];
    #pragma unroll
    for (int j = 0; j < 4; j++)
        #pragma unroll
        for (int c = 0; c < 4; c++) acc[j][c] = 0.f;

    for (int t = 0; t < SCHUNK / 64; t++) {
        const int st = t % 3;
        CP_WAIT(2);
        __syncthreads();
        const float* rK = (const float*)(smem + KA_RAW(st, 0));
        const float* rP = (const float*)(smem + KA_RAW(st, 1));
        const float4* rK4 = (const float4*)rK;
        const float4* rP4 = (const float4*)rP;
        const float4* rV4 = (const float4*)(smem + KA_RAW(st, 2));

        if (!uniform) {
            route_smem(rK, rP, sW, sLam, sLamRow, tid);
            __syncthreads();
        }
        // convert raw -> bf16 hi/lo swizzled tiles
        #pragma unroll
        for (int r = 0; r < 4; r++) {
            const int idx = tid + 256 * r;
            const int s = idx >> 4, c4 = idx & 15;
            float4 a = rK4[idx];
            float4 b = rP4[idx];
            const float l = uniform ? lam0 : sLamRow[s];
            float4 d;
            d.x = a.x - l * b.x;  d.y = a.y - l * b.y;
            d.z = a.z - l * b.z;  d.w = a.w - l * b.w;
            const u32 so = swoff(s, 4 * c4);
            u64 hi, lo;
            split4_u64(d, hi, lo);
            *(u64*)(smem + KA_KH + so) = hi;  *(u64*)(smem + KA_KL + so) = lo;
            split4_u64(rV4[idx], hi, lo);
            *(u64*)(smem + KA_VH + so) = hi;  *(u64*)(smem + KA_VL + so) = lo;
        }
        __syncthreads();
        // refill the stage we just consumed
        if (t + 3 < SCHUNK / 64)
            kv_issue(sb, st, Kt, Kp, Vg, base + (long)(t + 3) * 64 * ND, tid);
        CP_COMMIT();   // always commit so group indexing stays per-tile

        // MMA: A = Kd^T (m=d rows 16wd..), B = V^T (n=e cols 32we..)
        #pragma unroll
        for (int kk = 0; kk < 4; kk++) {
            const int k0 = 16 * kk;
            u32 aH[4], aL[4];
            const u32 aoff = swoff(k0 + (lane & 7) + 8 * (lane >> 4),
                                   16 * wd + 8 * ((lane >> 3) & 1));
            ldsm_x4_t(aH, kh + aoff);
            ldsm_x4_t(aL, kl + aoff);
            const int brow = k0 + (lane & 7) + 8 * ((lane >> 3) & 1);
            #pragma unroll
            for (int j = 0; j < 4; j++) {
                const u32 boff = swoff(brow, 32 * we + 8 * j);
                u32 bH0, bH1, bL0, bL1;
                ldsm_x2_t(bH0, bH1, vh + boff);
                ldsm_x2_t(bL0, bL1, vl + boff);
                mma16816(acc[j], aH, bH0, bH1);
                mma16816(acc[j], aH, bL0, bL1);
                mma16816(acc[j], aL, bH0, bH1);
            }
        }
        __syncthreads();
    }

    float* out = g_KVpart + ((long)chunk * NBH + bh) * (ND * ND);
    #pragma unroll
    for (int j = 0; j < 4; j++) {
        const int r0 = 16 * wd + g, e0 = 32 * we + 8 * j + 2 * t4;
        *(float2*)(out + r0 * ND + e0) = make_float2(acc[j][0], acc[j][1]);
        *(float2*)(out + (r0 + 8) * ND + e0) = make_float2(acc[j][2], acc[j][3]);
    }
}

// ==================== Reduce partials -> g_KV ====================
__global__ void __launch_bounds__(256) reduce_kernel()
{
    const int idx = blockIdx.x * 256 + threadIdx.x;   // over 65536 float4
    const float4* p = (const float4*)g_KVpart;
    float4 s = p[idx];
    #pragma unroll
    for (int c = 1; c < SCHUNKS; c++) {
        float4 v = p[(long)c * (NBH * ND * ND / 4) + idx];
        s.x += v.x; s.y += v.y; s.z += v.z; s.w += v.w;
    }
    ((float4*)g_KV)[idx] = s;
}

// ==================== Phase B: O = Qd @ KV, cp.async depth-2 pipeline ====================
#define OB_RAW(st, arr) (((st) * 2 + (arr)) * 16384)   // st 0..1; arr 0:Q 1:Q'
#define OB_QH 65536
#define OB_QL 73728
#define OB_BH 81920
#define OB_BL 90112
#define OB_W  98304
#define OB_LR 102912
#define OB_LM 103168
#define OB_UN 103232
#define OB_TOTAL 103296

__device__ __forceinline__ void out_issue(
    u32 sb, int stage,
    const float* __restrict__ gQ, const float* __restrict__ gP, long tb, int tid)
{
    const u32 dQ = sb + OB_RAW(stage, 0);
    const u32 dP = sb + OB_RAW(stage, 1);
    #pragma unroll
    for (int r = 0; r < 4; r++) {
        const int idx = tid + 256 * r;
        const u32 o = (u32)idx * 16;
        CP16(dQ + o, gQ + tb + (long)idx * 4);
        CP16(dP + o, gP + tb + (long)idx * 4);
    }
}

__global__ void __launch_bounds__(256) out_tc(
    const float* __restrict__ Qt, const float* __restrict__ Qp,
    const float* __restrict__ lambdas, const float* __restrict__ Wq,
    float* __restrict__ O)
{
    extern __shared__ char smem[];
    const u32 sb = smem_u32(smem);
    float* sW = (float*)(smem + OB_W);
    float* sLamRow = (float*)(smem + OB_LR);
    float* sLam = (float*)(smem + OB_LM);
    int* sUni = (int*)(smem + OB_UN);

    const int tid = threadIdx.x;
    const int stq = blockIdx.x, bh = blockIdx.y;
    const long base = ((long)bh * NS + (long)stq * 256) * ND;

    if (tid == 0) {
        float l0 = lambdas[0]; int u = 1;
        sLam[0] = l0;
        #pragma unroll
        for (int n = 1; n < NF; n++) { float v = lambdas[n]; sLam[n] = v; u &= (v == l0); }
        *sUni = u;
    }

    // prologue: issue Q tiles 0,1
    #pragma unroll
    for (int p = 0; p < 2; p++) {
        out_issue(sb, p, Qt, Qp, base + (long)p * 64 * ND, tid);
        CP_COMMIT();
    }

    // stage KV row-major [d][e] bf16 hi/lo (L2-resident)
    {
        const float* kv = g_KV + (long)bh * ND * ND;
        #pragma unroll
        for (int r = 0; r < 4; r++) {
            const int idx = tid + 256 * r;
            const int d = idx >> 4, c4 = idx & 15;
            float4 v = *(const float4*)(kv + d * ND + 4 * c4);
            u64 hi, lo; split4_u64(v, hi, lo);
            const u32 off = swoff(d, 4 * c4);
            *(u64*)(smem + OB_BH + off) = hi;
            *(u64*)(smem + OB_BL + off) = lo;
        }
    }
    __syncthreads();
    const bool uniform = (*sUni != 0);
    const float lam0 = sLam[0];
    if (!uniform) {
        for (int idx = tid; idx < NF * NDIM; idx += 256) sW[idx] = Wq[idx];
    }

    const int w = tid >> 5, lane = tid & 31;
    const int wd = w & 3, we = w >> 2;
    const int g = lane >> 2, t4 = lane & 3;
    const u32 qh = sb + OB_QH, ql = sb + OB_QL;
    const u32 bhp = sb + OB_BH, blp = sb + OB_BL;

    for (int t = 0; t < 4; t++) {
        const int st = t & 1;
        const long tb = base + (long)t * 64 * ND;
        CP_WAIT(1);
        __syncthreads();
        const float* rQ = (const float*)(smem + OB_RAW(st, 0));
        const float* rP = (const float*)(smem + OB_RAW(st, 1));
        const float4* rQ4 = (const float4*)rQ;
        const float4* rP4 = (const float4*)rP;

        if (!uniform) {
            route_smem(rQ, rP, sW, sLam, sLamRow, tid);
            __syncthreads();
        }
        #pragma unroll
        for (int r = 0; r < 4; r++) {
            const int idx = tid + 256 * r;
            const int s = idx >> 4, c4 = idx & 15;
            float4 a = rQ4[idx];
            float4 b = rP4[idx];
            const float l = uniform ? lam0 : sLamRow[s];
            float4 d;
            d.x = a.x - l * b.x;  d.y = a.y - l * b.y;
            d.z = a.z - l * b.z;  d.w = a.w - l * b.w;
            u64 hi, lo; split4_u64(d, hi, lo);
            const u32 off = swoff(s, 4 * c4);
            *(u64*)(smem + OB_QH + off) = hi;
            *(u64*)(smem + OB_QL + off) = lo;
        }
        __syncthreads();
        if (t + 2 < 4)
            out_issue(sb, st, Qt, Qp, base + (long)(t + 2) * 64 * ND, tid);
        CP_COMMIT();

        float acc[4][4];
        #pragma unroll
        for (int j = 0; j < 4; j++)
            #pragma unroll
            for (int c = 0; c < 4; c++) acc[j][c] = 0.f;

        // A = Qd row-major (non-trans), B = KV [d][e] -> trans
        #pragma unroll
        for (int kk = 0; kk < 4; kk++) {
            const int k0 = 16 * kk;
            u32 aH[4], aL[4];
            const u32 aoff = swoff(16 * wd + (lane & 15), k0 + 8 * (lane >> 4));
            ldsm_x4(aH, qh + aoff);
            ldsm_x4(aL, ql + aoff);
            const int brow = k0 + (lane & 7) + 8 * ((lane >> 3) & 1);
            #pragma unroll
            for (int j = 0; j < 4; j++) {
                const u32 boff = swoff(brow, 32 * we + 8 * j);
                u32 bH0, bH1, bL0, bL1;
                ldsm_x2_t(bH0, bH1, bhp + boff);
                ldsm_x2_t(bL0, bL1, blp + boff);
                mma16816(acc[j], aH, bH0, bH1);
                mma16816(acc[j], aH, bL0, bL1);
                mma16816(acc[j], aL, bH0, bH1);
            }
        }

        float* out = O + tb;
        #pragma unroll
        for (int j = 0; j < 4; j++) {
            const int r0 = 16 * wd + g, e0 = 32 * we + 8 * j + 2 * t4;
            *(float2*)(out + (long)r0 * ND + e0) = make_float2(acc[j][0], acc[j][1]);
            *(float2*)(out + (long)(r0 + 8) * ND + e0) = make_float2(acc[j][2], acc[j][3]);
        }
        __syncthreads();
    }
}

extern "C" void kernel_launch(void* const* d_in, const int* in_sizes, int n_in,
                              void* d_out, int out_size)
{
    const float* Qt  = (const float*)d_in[0];
    const float* Qp  = (const float*)d_in[1];
    const float* Kt  = (const float*)d_in[2];
    const float* Kp  = (const float*)d_in[3];
    const float* Vg  = (const float*)d_in[4];
    const float* lam = (const float*)d_in[5];
    const float* Wq  = (const float*)d_in[6];
    const float* Wk  = (const float*)d_in[7];
    float* O = (float*)d_out;

    static bool attr_set = false;
    if (!attr_set) {
        cudaFuncSetAttribute(kv_tc, cudaFuncAttributeMaxDynamicSharedMemorySize, KA_TOTAL);
        cudaFuncSetAttribute(out_tc, cudaFuncAttributeMaxDynamicSharedMemorySize, OB_TOTAL);
        attr_set = true;
    }

    kv_tc<<<dim3(SCHUNKS, NBH), 256, KA_TOTAL>>>(Kt, Kp, Vg, lam, Wk);
    reduce_kernel<<<(NBH * ND * ND / 4) / 256, 256>>>();
    out_tc<<<dim3(NS / 256, NBH), 256, OB_TOTAL>>>(Qt, Qp, lam, Wq, O);
}

// round 11
// speedup vs baseline: 1.2682x; 1.1565x over previous
#include <cuda_runtime.h>
#include <cuda_bf16.h>
#include <cstdint>

#define NS    4096
#define ND    64
#define NF    9
#define NDIM  128
#define NBH   64
#define SCHUNKS 16
#define SCHUNK  256
#define KTS     32          // kv_tc s-tile rows

__device__ float g_KVpart[SCHUNKS * NBH * ND * ND];  // 16.8 MB
__device__ float g_KV[NBH * ND * ND];                // 1 MB

typedef unsigned int u32;
typedef unsigned long long u64;

// ---------------- helpers ----------------
__device__ __forceinline__ u32 smem_u32(const void* p) {
    u32 a;
    asm("{ .reg .u64 t; cvta.to.shared.u64 t, %1; cvt.u32.u64 %0, t; }" : "=r"(a) : "l"(p));
    return a;
}

#define CP16(dst, src) \
    asm volatile("cp.async.cg.shared.global [%0], [%1], 16;" :: "r"(dst), "l"(src))
#define CP_COMMIT() asm volatile("cp.async.commit_group;" ::: "memory")
#define CP_WAIT(n)  asm volatile("cp.async.wait_group %0;" :: "n"(n) : "memory")

// Swizzled byte offset inside a [rows][64 bf16] tile (128B rows, 8 chunks of
// 16B, chunk ^= row&7). Conflict-free for u64 row-major stores AND ldmatrix.
__device__ __forceinline__ u32 swoff(int row, int col) {
    return (u32)((row << 7) + ((((col >> 3) ^ row) & 7) << 4) + ((col & 7) << 1));
}

__device__ __forceinline__ void split2(float x, float y, u32& hi, u32& lo) {
    __nv_bfloat16 hx = __float2bfloat16_rn(x);
    __nv_bfloat16 hy = __float2bfloat16_rn(y);
    __nv_bfloat16 lx = __float2bfloat16_rn(x - __bfloat162float(hx));
    __nv_bfloat16 ly = __float2bfloat16_rn(y - __bfloat162float(hy));
    hi = (u32)__bfloat16_as_ushort(hx) | ((u32)__bfloat16_as_ushort(hy) << 16);
    lo = (u32)__bfloat16_as_ushort(lx) | ((u32)__bfloat16_as_ushort(ly) << 16);
}
__device__ __forceinline__ void split4_u64(float4 v, u64& hi, u64& lo) {
    u32 h0, l0, h1, l1;
    split2(v.x, v.y, h0, l0);
    split2(v.z, v.w, h1, l1);
    hi = (u64)h0 | ((u64)h1 << 32);
    lo = (u64)l0 | ((u64)l1 << 32);
}

__device__ __forceinline__ void ldsm_x4(u32 r[4], u32 addr) {
    asm volatile("ldmatrix.sync.aligned.m8n8.x4.shared.b16 {%0,%1,%2,%3}, [%4];"
                 : "=r"(r[0]), "=r"(r[1]), "=r"(r[2]), "=r"(r[3]) : "r"(addr));
}
__device__ __forceinline__ void ldsm_x4_t(u32 r[4], u32 addr) {
    asm volatile("ldmatrix.sync.aligned.m8n8.x4.trans.shared.b16 {%0,%1,%2,%3}, [%4];"
                 : "=r"(r[0]), "=r"(r[1]), "=r"(r[2]), "=r"(r[3]) : "r"(addr));
}
__device__ __forceinline__ void ldsm_x2_t(u32& r0, u32& r1, u32 addr) {
    asm volatile("ldmatrix.sync.aligned.m8n8.x2.trans.shared.b16 {%0,%1}, [%2];"
                 : "=r"(r0), "=r"(r1) : "r"(addr));
}
__device__ __forceinline__ void mma16816(float* c, const u32* a, u32 b0, u32 b1) {
    asm volatile("mma.sync.aligned.m16n8k16.row.col.f32.bf16.bf16.f32 "
                 "{%0,%1,%2,%3}, {%4,%5,%6,%7}, {%8,%9}, {%0,%1,%2,%3};"
                 : "+f"(c[0]), "+f"(c[1]), "+f"(c[2]), "+f"(c[3])
                 : "r"(a[0]), "r"(a[1]), "r"(a[2]), "r"(a[3]), "r"(b0), "r"(b1));
}

// -------- routing from raw smem tiles: ROWS rows, 4 threads/row --------
template <int ROWS>
__device__ __forceinline__ void route_smem(
    const float* __restrict__ rX, const float* __restrict__ rP,
    const float* sW, const float* sLam, float* sLamRow, int tid)
{
    if (tid >= ROWS * 4) return;
    const int g = tid >> 2, q = tid & 3;
    const float* xptr = (q < 2) ? (rX + g * ND + 32 * q)
                                : (rP + g * ND + 32 * (q - 2));
    float sc[NF];
    #pragma unroll
    for (int n = 0; n < NF; n++) sc[n] = 0.f;
    #pragma unroll
    for (int e4 = 0; e4 < 8; e4++) {
        float4 xv = *(const float4*)(xptr + 4 * e4);
        #pragma unroll
        for (int n = 0; n < NF; n++) {
            float4 wv = *(const float4*)(sW + n * NDIM + 32 * q + 4 * e4);
            sc[n] += xv.x * wv.x + xv.y * wv.y + xv.z * wv.z + xv.w * wv.w;
        }
    }
    #pragma unroll
    for (int n = 0; n < NF; n++) {
        sc[n] += __shfl_xor_sync(0xffffffffu, sc[n], 1);
        sc[n] += __shfl_xor_sync(0xffffffffu, sc[n], 2);
    }
    int best = 0;
    #pragma unroll
    for (int n = 1; n < NF; n++) if (sc[n] > sc[best]) best = n;
    best = __shfl_sync(0xffffffffu, best, (tid & 31) & ~3);
    if (q == 0) sLamRow[g] = sLam[best];
}

// ==================== Phase A: KV partials, 32-row tiles, depth-3 cp.async ====================
// dyn smem (bytes): raw 3 stages x {K,K',V} x 8KB = 72KB, converted 16KB, misc
#define KA_RAW(st, arr) (((st) * 3 + (arr)) * 8192)
#define KA_KH 73728
#define KA_KL 77824
#define KA_VH 81920
#define KA_VL 86016
#define KA_W  90112
#define KA_LR 94720
#define KA_LM 94848
#define KA_UN 94912
#define KA_TOTAL 94976

__device__ __forceinline__ void kv_issue(
    u32 sb, int stage,
    const float* __restrict__ gK, const float* __restrict__ gP,
    const float* __restrict__ gV, long tb, int tid)
{
    const u32 dK = sb + KA_RAW(stage, 0);
    const u32 dP = sb + KA_RAW(stage, 1);
    const u32 dV = sb + KA_RAW(stage, 2);
    #pragma unroll
    for (int r = 0; r < 2; r++) {
        const int idx = tid + 256 * r;        // 16B chunk id, 512 per array
        const u32 o = (u32)idx * 16;
        CP16(dK + o, gK + tb + (long)idx * 4);
        CP16(dP + o, gP + tb + (long)idx * 4);
        CP16(dV + o, gV + tb + (long)idx * 4);
    }
}

__global__ void __launch_bounds__(256) kv_tc(
    const float* __restrict__ Kt, const float* __restrict__ Kp,
    const float* __restrict__ Vg, const float* __restrict__ lambdas,
    const float* __restrict__ Wk)
{
    extern __shared__ char smem[];
    const u32 sb = smem_u32(smem);
    float* sW = (float*)(smem + KA_W);
    float* sLamRow = (float*)(smem + KA_LR);
    float* sLam = (float*)(smem + KA_LM);
    int* sUni = (int*)(smem + KA_UN);

    const int tid = threadIdx.x;
    const int chunk = blockIdx.x, bh = blockIdx.y;

    if (tid == 0) {
        float l0 = lambdas[0]; int u = 1;
        #pragma unroll
        for (int n = 1; n < NF; n++) { float v = lambdas[n]; sLam[n] = v; u &= (v == l0); }
        sLam[0] = l0;
        *sUni = u;
    }
    const long base = ((long)bh * NS + (long)chunk * SCHUNK) * ND;

    // prologue: issue tiles 0,1,2
    #pragma unroll
    for (int p = 0; p < 3; p++) {
        kv_issue(sb, p, Kt, Kp, Vg, base + (long)p * KTS * ND, tid);
        CP_COMMIT();
    }
    __syncthreads();
    const bool uniform = (*sUni != 0);
    const float lam0 = sLam[0];
    if (!uniform) {
        for (int idx = tid; idx < NF * NDIM; idx += 256) sW[idx] = Wk[idx];
    }

    const int w = tid >> 5, lane = tid & 31;
    const int wd = w & 3, we = w >> 2;
    const int g = lane >> 2, t4 = lane & 3;
    const u32 kh = sb + KA_KH, kl = sb + KA_KL;
    const u32 vh = sb + KA_VH, vl = sb + KA_VL;

    float acc[4][4];
    #pragma unroll
    for (int j = 0; j < 4; j++)
        #pragma unroll
        for (int c = 0; c < 4; c++) acc[j][c] = 0.f;

    for (int t = 0; t < SCHUNK / KTS; t++) {
        const int st = t % 3;
        CP_WAIT(2);
        __syncthreads();
        const float* rK = (const float*)(smem + KA_RAW(st, 0));
        const float* rP = (const float*)(smem + KA_RAW(st, 1));
        const float4* rK4 = (const float4*)rK;
        const float4* rP4 = (const float4*)rP;
        const float4* rV4 = (const float4*)(smem + KA_RAW(st, 2));

        if (!uniform) {
            route_smem<KTS>(rK, rP, sW, sLam, sLamRow, tid);
            __syncthreads();
        }
        // convert raw -> bf16 hi/lo swizzled tiles (512 float4 per array)
        #pragma unroll
        for (int r = 0; r < 2; r++) {
            const int idx = tid + 256 * r;
            const int s = idx >> 4, c4 = idx & 15;
            float4 a = rK4[idx];
            float4 b = rP4[idx];
            const float l = uniform ? lam0 : sLamRow[s];
            float4 d;
            d.x = a.x - l * b.x;  d.y = a.y - l * b.y;
            d.z = a.z - l * b.z;  d.w = a.w - l * b.w;
            const u32 so = swoff(s, 4 * c4);
            u64 hi, lo;
            split4_u64(d, hi, lo);
            *(u64*)(smem + KA_KH + so) = hi;  *(u64*)(smem + KA_KL + so) = lo;
            split4_u64(rV4[idx], hi, lo);
            *(u64*)(smem + KA_VH + so) = hi;  *(u64*)(smem + KA_VL + so) = lo;
        }
        __syncthreads();
        // refill the stage we just consumed
        if (t + 3 < SCHUNK / KTS)
            kv_issue(sb, st, Kt, Kp, Vg, base + (long)(t + 3) * KTS * ND, tid);
        CP_COMMIT();   // always commit so group indexing stays per-tile

        // MMA: A = Kd^T (m=d rows 16wd..), B = V^T (n=e cols 32we..), K-dim 32
        #pragma unroll
        for (int kk = 0; kk < 2; kk++) {
            const int k0 = 16 * kk;
            u32 aH[4], aL[4];
            const u32 aoff = swoff(k0 + (lane & 7) + 8 * (lane >> 4),
                                   16 * wd + 8 * ((lane >> 3) & 1));
            ldsm_x4_t(aH, kh + aoff);
            ldsm_x4_t(aL, kl + aoff);
            const int brow = k0 + (lane & 7) + 8 * ((lane >> 3) & 1);
            #pragma unroll
            for (int j = 0; j < 4; j++) {
                const u32 boff = swoff(brow, 32 * we + 8 * j);
                u32 bH0, bH1, bL0, bL1;
                ldsm_x2_t(bH0, bH1, vh + boff);
                ldsm_x2_t(bL0, bL1, vl + boff);
                mma16816(acc[j], aH, bH0, bH1);
                mma16816(acc[j], aH, bL0, bL1);
                mma16816(acc[j], aL, bH0, bH1);
            }
        }
        __syncthreads();
    }

    float* out = g_KVpart + ((long)chunk * NBH + bh) * (ND * ND);
    #pragma unroll
    for (int j = 0; j < 4; j++) {
        const int r0 = 16 * wd + g, e0 = 32 * we + 8 * j + 2 * t4;
        *(float2*)(out + r0 * ND + e0) = make_float2(acc[j][0], acc[j][1]);
        *(float2*)(out + (r0 + 8) * ND + e0) = make_float2(acc[j][2], acc[j][3]);
    }
}

// ==================== Reduce partials -> g_KV ====================
__global__ void __launch_bounds__(256) reduce_kernel()
{
    const int idx = blockIdx.x * 256 + threadIdx.x;   // over 65536 float4
    const float4* p = (const float4*)g_KVpart;
    float4 s = p[idx];
    #pragma unroll
    for (int c = 1; c < SCHUNKS; c++) {
        float4 v = p[(long)c * (NBH * ND * ND / 4) + idx];
        s.x += v.x; s.y += v.y; s.z += v.z; s.w += v.w;
    }
    ((float4*)g_KV)[idx] = s;
}

// ==================== Phase B: O = Qd @ KV, cp.async depth-2 pipeline ====================
#define OB_RAW(st, arr) (((st) * 2 + (arr)) * 16384)   // st 0..1; arr 0:Q 1:Q'
#define OB_QH 65536
#define OB_QL 73728
#define OB_BH 81920
#define OB_BL 90112
#define OB_W  98304
#define OB_LR 102912
#define OB_LM 103168
#define OB_UN 103232
#define OB_TOTAL 103296

__device__ __forceinline__ void out_issue(
    u32 sb, int stage,
    const float* __restrict__ gQ, const float* __restrict__ gP, long tb, int tid)
{
    const u32 dQ = sb + OB_RAW(stage, 0);
    const u32 dP = sb + OB_RAW(stage, 1);
    #pragma unroll
    for (int r = 0; r < 4; r++) {
        const int idx = tid + 256 * r;
        const u32 o = (u32)idx * 16;
        CP16(dQ + o, gQ + tb + (long)idx * 4);
        CP16(dP + o, gP + tb + (long)idx * 4);
    }
}

__global__ void __launch_bounds__(256) out_tc(
    const float* __restrict__ Qt, const float* __restrict__ Qp,
    const float* __restrict__ lambdas, const float* __restrict__ Wq,
    float* __restrict__ O)
{
    extern __shared__ char smem[];
    const u32 sb = smem_u32(smem);
    float* sW = (float*)(smem + OB_W);
    float* sLamRow = (float*)(smem + OB_LR);
    float* sLam = (float*)(smem + OB_LM);
    int* sUni = (int*)(smem + OB_UN);

    const int tid = threadIdx.x;
    const int stq = blockIdx.x, bh = blockIdx.y;
    const long base = ((long)bh * NS + (long)stq * 256) * ND;

    if (tid == 0) {
        float l0 = lambdas[0]; int u = 1;
        #pragma unroll
        for (int n = 1; n < NF; n++) { float v = lambdas[n]; sLam[n] = v; u &= (v == l0); }
        sLam[0] = l0;
        *sUni = u;
    }

    // prologue: issue Q tiles 0,1
    #pragma unroll
    for (int p = 0; p < 2; p++) {
        out_issue(sb, p, Qt, Qp, base + (long)p * 64 * ND, tid);
        CP_COMMIT();
    }

    // stage KV row-major [d][e] bf16 hi/lo (L2-resident)
    {
        const float* kv = g_KV + (long)bh * ND * ND;
        #pragma unroll
        for (int r = 0; r < 4; r++) {
            const int idx = tid + 256 * r;
            const int d = idx >> 4, c4 = idx & 15;
            float4 v = *(const float4*)(kv + d * ND + 4 * c4);
            u64 hi, lo; split4_u64(v, hi, lo);
            const u32 off = swoff(d, 4 * c4);
            *(u64*)(smem + OB_BH + off) = hi;
            *(u64*)(smem + OB_BL + off) = lo;
        }
    }
    __syncthreads();
    const bool uniform = (*sUni != 0);
    const float lam0 = sLam[0];
    if (!uniform) {
        for (int idx = tid; idx < NF * NDIM; idx += 256) sW[idx] = Wq[idx];
    }

    const int w = tid >> 5, lane = tid & 31;
    const int wd = w & 3, we = w >> 2;
    const int g = lane >> 2, t4 = lane & 3;
    const u32 qh = sb + OB_QH, ql = sb + OB_QL;
    const u32 bhp = sb + OB_BH, blp = sb + OB_BL;

    for (int t = 0; t < 4; t++) {
        const int st = t & 1;
        const long tb = base + (long)t * 64 * ND;
        CP_WAIT(1);
        __syncthreads();
        const float* rQ = (const float*)(smem + OB_RAW(st, 0));
        const float* rP = (const float*)(smem + OB_RAW(st, 1));
        const float4* rQ4 = (const float4*)rQ;
        const float4* rP4 = (const float4*)rP;

        if (!uniform) {
            route_smem<64>(rQ, rP, sW, sLam, sLamRow, tid);
            __syncthreads();
        }
        #pragma unroll
        for (int r = 0; r < 4; r++) {
            const int idx = tid + 256 * r;
            const int s = idx >> 4, c4 = idx & 15;
            float4 a = rQ4[idx];
            float4 b = rP4[idx];
            const float l = uniform ? lam0 : sLamRow[s];
            float4 d;
            d.x = a.x - l * b.x;  d.y = a.y - l * b.y;
            d.z = a.z - l * b.z;  d.w = a.w - l * b.w;
            u64 hi, lo; split4_u64(d, hi, lo);
            const u32 off = swoff(s, 4 * c4);
            *(u64*)(smem + OB_QH + off) = hi;
            *(u64*)(smem + OB_QL + off) = lo;
        }
        __syncthreads();
        if (t + 2 < 4)
            out_issue(sb, st, Qt, Qp, base + (long)(t + 2) * 64 * ND, tid);
        CP_COMMIT();

        float acc[4][4];
        #pragma unroll
        for (int j = 0; j < 4; j++)
            #pragma unroll
            for (int c = 0; c < 4; c++) acc[j][c] = 0.f;

        // A = Qd row-major (non-trans), B = KV [d][e] -> trans
        #pragma unroll
        for (int kk = 0; kk < 4; kk++) {
            const int k0 = 16 * kk;
            u32 aH[4], aL[4];
            const u32 aoff = swoff(16 * wd + (lane & 15), k0 + 8 * (lane >> 4));
            ldsm_x4(aH, qh + aoff);
            ldsm_x4(aL, ql + aoff);
            const int brow = k0 + (lane & 7) + 8 * ((lane >> 3) & 1);
            #pragma unroll
            for (int j = 0; j < 4; j++) {
                const u32 boff = swoff(brow, 32 * we + 8 * j);
                u32 bH0, bH1, bL0, bL1;
                ldsm_x2_t(bH0, bH1, bhp + boff);
                ldsm_x2_t(bL0, bL1, blp + boff);
                mma16816(acc[j], aH, bH0, bH1);
                mma16816(acc[j], aH, bL0, bL1);
                mma16816(acc[j], aL, bH0, bH1);
            }
        }

        float* out = O + tb;
        #pragma unroll
        for (int j = 0; j < 4; j++) {
            const int r0 = 16 * wd + g, e0 = 32 * we + 8 * j + 2 * t4;
            *(float2*)(out + (long)r0 * ND + e0) = make_float2(acc[j][0], acc[j][1]);
            *(float2*)(out + (long)(r0 + 8) * ND + e0) = make_float2(acc[j][2], acc[j][3]);
        }
        __syncthreads();
    }
}

extern "C" void kernel_launch(void* const* d_in, const int* in_sizes, int n_in,
                              void* d_out, int out_size)
{
    const float* Qt  = (const float*)d_in[0];
    const float* Qp  = (const float*)d_in[1];
    const float* Kt  = (const float*)d_in[2];
    const float* Kp  = (const float*)d_in[3];
    const float* Vg  = (const float*)d_in[4];
    const float* lam = (const float*)d_in[5];
    const float* Wq  = (const float*)d_in[6];
    const float* Wk  = (const float*)d_in[7];
    float* O = (float*)d_out;

    static bool attr_set = false;
    if (!attr_set) {
        cudaFuncSetAttribute(kv_tc, cudaFuncAttributeMaxDynamicSharedMemorySize, KA_TOTAL);
        cudaFuncSetAttribute(out_tc, cudaFuncAttributeMaxDynamicSharedMemorySize, OB_TOTAL);
        attr_set = true;
    }

    kv_tc<<<dim3(SCHUNKS, NBH), 256, KA_TOTAL>>>(Kt, Kp, Vg, lam, Wk);
    reduce_kernel<<<(NBH * ND * ND / 4) / 256, 256>>>();
    out_tc<<<dim3(NS / 256, NBH), 256, OB_TOTAL>>>(Qt, Qp, lam, Wq, O);
}

// round 12
// speedup vs baseline: 1.2995x; 1.0247x over previous
#include <cuda_runtime.h>
#include <cuda_bf16.h>
#include <cstdint>

#define NS    4096
#define ND    64
#define NF    9
#define NDIM  128
#define NBH   64
#define SCHUNKS 16
#define SCHUNK  256
#define KTS     32          // kv_tc s-tile rows

__device__ float g_KVpart[SCHUNKS * NBH * ND * ND];  // 16.8 MB
__device__ float g_KV[NBH * ND * ND];                // 1 MB

typedef unsigned int u32;
typedef unsigned long long u64;

// ---------------- helpers ----------------
__device__ __forceinline__ u32 smem_u32(const void* p) {
    u32 a;
    asm("{ .reg .u64 t; cvta.to.shared.u64 t, %1; cvt.u32.u64 %0, t; }" : "=r"(a) : "l"(p));
    return a;
}

#define CP16(dst, src) \
    asm volatile("cp.async.cg.shared.global [%0], [%1], 16;" :: "r"(dst), "l"(src))
#define CP_COMMIT() asm volatile("cp.async.commit_group;" ::: "memory")
#define CP_WAIT(n)  asm volatile("cp.async.wait_group %0;" :: "n"(n) : "memory")

// Swizzled byte offset inside a [rows][64 bf16] tile (128B rows, 8 chunks of
// 16B, chunk ^= row&7). Conflict-free for u64 row-major stores AND ldmatrix.
__device__ __forceinline__ u32 swoff(int row, int col) {
    return (u32)((row << 7) + ((((col >> 3) ^ row) & 7) << 4) + ((col & 7) << 1));
}

__device__ __forceinline__ void split2(float x, float y, u32& hi, u32& lo) {
    __nv_bfloat16 hx = __float2bfloat16_rn(x);
    __nv_bfloat16 hy = __float2bfloat16_rn(y);
    __nv_bfloat16 lx = __float2bfloat16_rn(x - __bfloat162float(hx));
    __nv_bfloat16 ly = __float2bfloat16_rn(y - __bfloat162float(hy));
    hi = (u32)__bfloat16_as_ushort(hx) | ((u32)__bfloat16_as_ushort(hy) << 16);
    lo = (u32)__bfloat16_as_ushort(lx) | ((u32)__bfloat16_as_ushort(ly) << 16);
}
__device__ __forceinline__ void split4_u64(float4 v, u64& hi, u64& lo) {
    u32 h0, l0, h1, l1;
    split2(v.x, v.y, h0, l0);
    split2(v.z, v.w, h1, l1);
    hi = (u64)h0 | ((u64)h1 << 32);
    lo = (u64)l0 | ((u64)l1 << 32);
}

__device__ __forceinline__ void ldsm_x4(u32 r[4], u32 addr) {
    asm volatile("ldmatrix.sync.aligned.m8n8.x4.shared.b16 {%0,%1,%2,%3}, [%4];"
                 : "=r"(r[0]), "=r"(r[1]), "=r"(r[2]), "=r"(r[3]) : "r"(addr));
}
__device__ __forceinline__ void ldsm_x4_t(u32 r[4], u32 addr) {
    asm volatile("ldmatrix.sync.aligned.m8n8.x4.trans.shared.b16 {%0,%1,%2,%3}, [%4];"
                 : "=r"(r[0]), "=r"(r[1]), "=r"(r[2]), "=r"(r[3]) : "r"(addr));
}
__device__ __forceinline__ void ldsm_x2_t(u32& r0, u32& r1, u32 addr) {
    asm volatile("ldmatrix.sync.aligned.m8n8.x2.trans.shared.b16 {%0,%1}, [%2];"
                 : "=r"(r0), "=r"(r1) : "r"(addr));
}
__device__ __forceinline__ void mma16816(float* c, const u32* a, u32 b0, u32 b1) {
    asm volatile("mma.sync.aligned.m16n8k16.row.col.f32.bf16.bf16.f32 "
                 "{%0,%1,%2,%3}, {%4,%5,%6,%7}, {%8,%9}, {%0,%1,%2,%3};"
                 : "+f"(c[0]), "+f"(c[1]), "+f"(c[2]), "+f"(c[3])
                 : "r"(a[0]), "r"(a[1]), "r"(a[2]), "r"(a[3]), "r"(b0), "r"(b1));
}

// -------- routing from raw smem tiles: ROWS rows, 4 threads/row --------
template <int ROWS>
__device__ __forceinline__ void route_smem(
    const float* __restrict__ rX, const float* __restrict__ rP,
    const float* sW, const float* sLam, float* sLamRow, int tid)
{
    if (tid >= ROWS * 4) return;
    const int g = tid >> 2, q = tid & 3;
    const float* xptr = (q < 2) ? (rX + g * ND + 32 * q)
                                : (rP + g * ND + 32 * (q - 2));
    float sc[NF];
    #pragma unroll
    for (int n = 0; n < NF; n++) sc[n] = 0.f;
    #pragma unroll
    for (int e4 = 0; e4 < 8; e4++) {
        float4 xv = *(const float4*)(xptr + 4 * e4);
        #pragma unroll
        for (int n = 0; n < NF; n++) {
            float4 wv = *(const float4*)(sW + n * NDIM + 32 * q + 4 * e4);
            sc[n] += xv.x * wv.x + xv.y * wv.y + xv.z * wv.z + xv.w * wv.w;
        }
    }
    #pragma unroll
    for (int n = 0; n < NF; n++) {
        sc[n] += __shfl_xor_sync(0xffffffffu, sc[n], 1);
        sc[n] += __shfl_xor_sync(0xffffffffu, sc[n], 2);
    }
    int best = 0;
    #pragma unroll
    for (int n = 1; n < NF; n++) if (sc[n] > sc[best]) best = n;
    best = __shfl_sync(0xffffffffu, best, (tid & 31) & ~3);
    if (q == 0) sLamRow[g] = sLam[best];
}

// ==================== Phase A: KV partials, 32-row tiles, depth-2 cp.async ====================
// dyn smem (bytes): raw 2 stages x {K,K',V} x 8KB = 48KB + conv 16KB + misc -> 3 blocks/SM
#define KA_RAW(st, arr) (((st) * 3 + (arr)) * 8192)
#define KA_KH 49152
#define KA_KL 53248
#define KA_VH 57344
#define KA_VL 61440
#define KA_W  65536
#define KA_LR 70144
#define KA_LM 70272
#define KA_UN 70336
#define KA_TOTAL 70400

__device__ __forceinline__ void kv_issue(
    u32 sb, int stage,
    const float* __restrict__ gK, const float* __restrict__ gP,
    const float* __restrict__ gV, long tb, int tid)
{
    const u32 dK = sb + KA_RAW(stage, 0);
    const u32 dP = sb + KA_RAW(stage, 1);
    const u32 dV = sb + KA_RAW(stage, 2);
    #pragma unroll
    for (int r = 0; r < 2; r++) {
        const int idx = tid + 256 * r;        // 16B chunk id, 512 per array
        const u32 o = (u32)idx * 16;
        CP16(dK + o, gK + tb + (long)idx * 4);
        CP16(dP + o, gP + tb + (long)idx * 4);
        CP16(dV + o, gV + tb + (long)idx * 4);
    }
}

__global__ void __launch_bounds__(256) kv_tc(
    const float* __restrict__ Kt, const float* __restrict__ Kp,
    const float* __restrict__ Vg, const float* __restrict__ lambdas,
    const float* __restrict__ Wk)
{
    extern __shared__ char smem[];
    const u32 sb = smem_u32(smem);
    float* sW = (float*)(smem + KA_W);
    float* sLamRow = (float*)(smem + KA_LR);
    float* sLam = (float*)(smem + KA_LM);
    int* sUni = (int*)(smem + KA_UN);

    const int tid = threadIdx.x;
    const int chunk = blockIdx.x, bh = blockIdx.y;

    if (tid == 0) {
        float l0 = lambdas[0]; int u = 1;
        #pragma unroll
        for (int n = 1; n < NF; n++) { float v = lambdas[n]; sLam[n] = v; u &= (v == l0); }
        sLam[0] = l0;
        *sUni = u;
    }
    const long base = ((long)bh * NS + (long)chunk * SCHUNK) * ND;

    // prologue: issue tiles 0,1
    #pragma unroll
    for (int p = 0; p < 2; p++) {
        kv_issue(sb, p, Kt, Kp, Vg, base + (long)p * KTS * ND, tid);
        CP_COMMIT();
    }
    __syncthreads();
    const bool uniform = (*sUni != 0);
    const float lam0 = sLam[0];
    if (!uniform) {
        for (int idx = tid; idx < NF * NDIM; idx += 256) sW[idx] = Wk[idx];
    }

    const int w = tid >> 5, lane = tid & 31;
    const int wd = w & 3, we = w >> 2;
    const int g = lane >> 2, t4 = lane & 3;
    const u32 kh = sb + KA_KH, kl = sb + KA_KL;
    const u32 vh = sb + KA_VH, vl = sb + KA_VL;

    float acc[4][4];
    #pragma unroll
    for (int j = 0; j < 4; j++)
        #pragma unroll
        for (int c = 0; c < 4; c++) acc[j][c] = 0.f;

    for (int t = 0; t < SCHUNK / KTS; t++) {
        const int st = t & 1;
        CP_WAIT(1);
        __syncthreads();
        const float* rK = (const float*)(smem + KA_RAW(st, 0));
        const float* rP = (const float*)(smem + KA_RAW(st, 1));
        const float4* rK4 = (const float4*)rK;
        const float4* rP4 = (const float4*)rP;
        const float4* rV4 = (const float4*)(smem + KA_RAW(st, 2));

        if (!uniform) {
            route_smem<KTS>(rK, rP, sW, sLam, sLamRow, tid);
            __syncthreads();
        }
        // convert raw -> bf16 hi/lo swizzled tiles (512 float4 per array)
        #pragma unroll
        for (int r = 0; r < 2; r++) {
            const int idx = tid + 256 * r;
            const int s = idx >> 4, c4 = idx & 15;
            float4 a = rK4[idx];
            float4 b = rP4[idx];
            const float l = uniform ? lam0 : sLamRow[s];
            float4 d;
            d.x = a.x - l * b.x;  d.y = a.y - l * b.y;
            d.z = a.z - l * b.z;  d.w = a.w - l * b.w;
            const u32 so = swoff(s, 4 * c4);
            u64 hi, lo;
            split4_u64(d, hi, lo);
            *(u64*)(smem + KA_KH + so) = hi;  *(u64*)(smem + KA_KL + so) = lo;
            split4_u64(rV4[idx], hi, lo);
            *(u64*)(smem + KA_VH + so) = hi;  *(u64*)(smem + KA_VL + so) = lo;
        }
        __syncthreads();
        // refill the stage we just consumed
        if (t + 2 < SCHUNK / KTS)
            kv_issue(sb, st, Kt, Kp, Vg, base + (long)(t + 2) * KTS * ND, tid);
        CP_COMMIT();   // always commit so group indexing stays per-tile

        // MMA: A = Kd^T (m=d rows 16wd..), B = V^T (n=e cols 32we..), K-dim 32
        #pragma unroll
        for (int kk = 0; kk < 2; kk++) {
            const int k0 = 16 * kk;
            u32 aH[4], aL[4];
            const u32 aoff = swoff(k0 + (lane & 7) + 8 * (lane >> 4),
                                   16 * wd + 8 * ((lane >> 3) & 1));
            ldsm_x4_t(aH, kh + aoff);
            ldsm_x4_t(aL, kl + aoff);
            const int brow = k0 + (lane & 7) + 8 * ((lane >> 3) & 1);
            #pragma unroll
            for (int j = 0; j < 4; j++) {
                const u32 boff = swoff(brow, 32 * we + 8 * j);
                u32 bH0, bH1, bL0, bL1;
                ldsm_x2_t(bH0, bH1, vh + boff);
                ldsm_x2_t(bL0, bL1, vl + boff);
                mma16816(acc[j], aH, bH0, bH1);
                mma16816(acc[j], aH, bL0, bL1);
                mma16816(acc[j], aL, bH0, bH1);
            }
        }
        __syncthreads();
    }

    float* out = g_KVpart + ((long)chunk * NBH + bh) * (ND * ND);
    #pragma unroll
    for (int j = 0; j < 4; j++) {
        const int r0 = 16 * wd + g, e0 = 32 * we + 8 * j + 2 * t4;
        *(float2*)(out + r0 * ND + e0) = make_float2(acc[j][0], acc[j][1]);
        *(float2*)(out + (r0 + 8) * ND + e0) = make_float2(acc[j][2], acc[j][3]);
    }
}

// ==================== Reduce partials -> g_KV ====================
__global__ void __launch_bounds__(256) reduce_kernel()
{
    const int idx = blockIdx.x * 256 + threadIdx.x;   // over 65536 float4
    const float4* p = (const float4*)g_KVpart;
    float4 s = p[idx];
    #pragma unroll
    for (int c = 1; c < SCHUNKS; c++) {
        float4 v = p[(long)c * (NBH * ND * ND / 4) + idx];
        s.x += v.x; s.y += v.y; s.z += v.z; s.w += v.w;
    }
    ((float4*)g_KV)[idx] = s;
}

// ==================== Phase B: O = Qd @ KV, 32-row tiles, depth-2 cp.async ====================
#define OB_RAW(st, arr) (((st) * 2 + (arr)) * 8192)   // st 0..1; arr 0:Q 1:Q'
#define OB_QH 32768
#define OB_QL 36864
#define OB_BH 40960
#define OB_BL 49152
#define OB_W  57344
#define OB_LR 61952
#define OB_LM 62080
#define OB_UN 62144
#define OB_TOTAL 62208

__device__ __forceinline__ void out_issue(
    u32 sb, int stage,
    const float* __restrict__ gQ, const float* __restrict__ gP, long tb, int tid)
{
    const u32 dQ = sb + OB_RAW(stage, 0);
    const u32 dP = sb + OB_RAW(stage, 1);
    #pragma unroll
    for (int r = 0; r < 2; r++) {
        const int idx = tid + 256 * r;     // 512 chunks of 16B per array
        const u32 o = (u32)idx * 16;
        CP16(dQ + o, gQ + tb + (long)idx * 4);
        CP16(dP + o, gP + tb + (long)idx * 4);
    }
}

__global__ void __launch_bounds__(256) out_tc(
    const float* __restrict__ Qt, const float* __restrict__ Qp,
    const float* __restrict__ lambdas, const float* __restrict__ Wq,
    float* __restrict__ O)
{
    extern __shared__ char smem[];
    const u32 sb = smem_u32(smem);
    float* sW = (float*)(smem + OB_W);
    float* sLamRow = (float*)(smem + OB_LR);
    float* sLam = (float*)(smem + OB_LM);
    int* sUni = (int*)(smem + OB_UN);

    const int tid = threadIdx.x;
    const int stq = blockIdx.x, bh = blockIdx.y;
    const long base = ((long)bh * NS + (long)stq * 256) * ND;

    if (tid == 0) {
        float l0 = lambdas[0]; int u = 1;
        #pragma unroll
        for (int n = 1; n < NF; n++) { float v = lambdas[n]; sLam[n] = v; u &= (v == l0); }
        sLam[0] = l0;
        *sUni = u;
    }

    // prologue: issue Q tiles 0,1
    #pragma unroll
    for (int p = 0; p < 2; p++) {
        out_issue(sb, p, Qt, Qp, base + (long)p * KTS * ND, tid);
        CP_COMMIT();
    }

    // stage KV row-major [d][e] bf16 hi/lo (L2-resident)
    {
        const float* kv = g_KV + (long)bh * ND * ND;
        #pragma unroll
        for (int r = 0; r < 4; r++) {
            const int idx = tid + 256 * r;
            const int d = idx >> 4, c4 = idx & 15;
            float4 v = *(const float4*)(kv + d * ND + 4 * c4);
            u64 hi, lo; split4_u64(v, hi, lo);
            const u32 off = swoff(d, 4 * c4);
            *(u64*)(smem + OB_BH + off) = hi;
            *(u64*)(smem + OB_BL + off) = lo;
        }
    }
    __syncthreads();
    const bool uniform = (*sUni != 0);
    const float lam0 = sLam[0];
    if (!uniform) {
        for (int idx = tid; idx < NF * NDIM; idx += 256) sW[idx] = Wq[idx];
    }

    const int w = tid >> 5, lane = tid & 31;
    const int wd = w & 1, we = w >> 1;         // 2 row-halves x 4 col-groups
    const int g = lane >> 2, t4 = lane & 3;
    const u32 qh = sb + OB_QH, ql = sb + OB_QL;
    const u32 bhp = sb + OB_BH, blp = sb + OB_BL;

    for (int t = 0; t < 8; t++) {
        const int st = t & 1;
        const long tb = base + (long)t * KTS * ND;
        CP_WAIT(1);
        __syncthreads();
        const float* rQ = (const float*)(smem + OB_RAW(st, 0));
        const float* rP = (const float*)(smem + OB_RAW(st, 1));
        const float4* rQ4 = (const float4*)rQ;
        const float4* rP4 = (const float4*)rP;

        if (!uniform) {
            route_smem<KTS>(rQ, rP, sW, sLam, sLamRow, tid);
            __syncthreads();
        }
        #pragma unroll
        for (int r = 0; r < 2; r++) {
            const int idx = tid + 256 * r;
            const int s = idx >> 4, c4 = idx & 15;
            float4 a = rQ4[idx];
            float4 b = rP4[idx];
            const float l = uniform ? lam0 : sLamRow[s];
            float4 d;
            d.x = a.x - l * b.x;  d.y = a.y - l * b.y;
            d.z = a.z - l * b.z;  d.w = a.w - l * b.w;
            u64 hi, lo; split4_u64(d, hi, lo);
            const u32 off = swoff(s, 4 * c4);
            *(u64*)(smem + OB_QH + off) = hi;
            *(u64*)(smem + OB_QL + off) = lo;
        }
        __syncthreads();
        if (t + 2 < 8)
            out_issue(sb, st, Qt, Qp, base + (long)(t + 2) * KTS * ND, tid);
        CP_COMMIT();

        float acc[2][4];
        #pragma unroll
        for (int j = 0; j < 2; j++)
            #pragma unroll
            for (int c = 0; c < 4; c++) acc[j][c] = 0.f;

        // A = Qd row-major (non-trans, rows 16wd..), B = KV [d][e] -> trans
        #pragma unroll
        for (int kk = 0; kk < 4; kk++) {
            const int k0 = 16 * kk;
            u32 aH[4], aL[4];
            const u32 aoff = swoff(16 * wd + (lane & 15), k0 + 8 * (lane >> 4));
            ldsm_x4(aH, qh + aoff);
            ldsm_x4(aL, ql + aoff);
            const int brow = k0 + (lane & 7) + 8 * ((lane >> 3) & 1);
            #pragma unroll
            for (int j = 0; j < 2; j++) {
                const u32 boff = swoff(brow, 16 * we + 8 * j);
                u32 bH0, bH1, bL0, bL1;
                ldsm_x2_t(bH0, bH1, bhp + boff);
                ldsm_x2_t(bL0, bL1, blp + boff);
                mma16816(acc[j], aH, bH0, bH1);
                mma16816(acc[j], aH, bL0, bL1);
                mma16816(acc[j], aL, bH0, bH1);
            }
        }

        float* out = O + tb;
        #pragma unroll
        for (int j = 0; j < 2; j++) {
            const int r0 = 16 * wd + g, e0 = 16 * we + 8 * j + 2 * t4;
            *(float2*)(out + (long)r0 * ND + e0) = make_float2(acc[j][0], acc[j][1]);
            *(float2*)(out + (long)(r0 + 8) * ND + e0) = make_float2(acc[j][2], acc[j][3]);
        }
        __syncthreads();
    }
}

extern "C" void kernel_launch(void* const* d_in, const int* in_sizes, int n_in,
                              void* d_out, int out_size)
{
    const float* Qt  = (const float*)d_in[0];
    const float* Qp  = (const float*)d_in[1];
    const float* Kt  = (const float*)d_in[2];
    const float* Kp  = (const float*)d_in[3];
    const float* Vg  = (const float*)d_in[4];
    const float* lam = (const float*)d_in[5];
    const float* Wq  = (const float*)d_in[6];
    const float* Wk  = (const float*)d_in[7];
    float* O = (float*)d_out;

    static bool attr_set = false;
    if (!attr_set) {
        cudaFuncSetAttribute(kv_tc, cudaFuncAttributeMaxDynamicSharedMemorySize, KA_TOTAL);
        cudaFuncSetAttribute(out_tc, cudaFuncAttributeMaxDynamicSharedMemorySize, OB_TOTAL);
        attr_set = true;
    }

    kv_tc<<<dim3(SCHUNKS, NBH), 256, KA_TOTAL>>>(Kt, Kp, Vg, lam, Wk);
    reduce_kernel<<<(NBH * ND * ND / 4) / 256, 256>>>();
    out_tc<<<dim3(NS / 256, NBH), 256, OB_TOTAL>>>(Qt, Qp, lam, Wq, O);
}